// round 15
// baseline (speedup 1.0000x reference)
#include <cuda_runtime.h>
#include <cstdint>

#define Bb   128
#define Lq   128
#define Iin  256
#define Hh   256
#define G4   1024
#define Kd   512

#define OUT_ELEMS (Bb*Lq*Hh)
#define HF_OFF (OUT_ELEMS)
#define CF_OFF (OUT_ELEMS + 2*Bb*Hh)
#define KL_OFF (OUT_ELEMS + 4*Bb*Hh)

// -------- scratch --------
__device__ float g_std0[G4*Kd];   // pexp(0.5*logvar)
__device__ float g_std1[G4*Kd];
__device__ float g_bstd0[G4], g_bstd1[G4];
__device__ float g_h0[Lq*Bb*Hh];
__device__ float g_c0[Bb*Hh];
__device__ float g_c1[Bb*Hh];

__device__ const float* g_pwmu0;
__device__ const float* g_pwlv0;
__device__ const float* g_pwmu1;
__device__ const float* g_pwlv1;
__device__ const float* g_pbmu0;
__device__ const float* g_pblv0;
__device__ const float* g_pbmu1;
__device__ const float* g_pblv1;

// ---- FROZEN: Cephes/XLA pexp, fma-contracted, clamp +-88.3762626647949 ----
__device__ __forceinline__ float pexp_fma(float x) {
    x = fminf(fmaxf(x, -88.3762626647949f), 88.3762626647949f);
    float m = floorf(fmaf(x, 1.44269504088896341f, 0.5f));
    float r = fmaf(m, -0.693359375f, x);
    r = fmaf(m, 2.12194440e-4f, r);
    float r2 = __fmul_rn(r, r);
    float p = 1.9875691500e-4f;
    p = fmaf(p, r, 1.3981999507e-3f);
    p = fmaf(p, r, 8.3334519073e-3f);
    p = fmaf(p, r, 4.1665795894e-2f);
    p = fmaf(p, r, 1.6666665459e-1f);
    p = fmaf(p, r, 5.0000001201e-1f);
    p = fmaf(p, r2, r);
    p = __fadd_rn(p, 1.0f);
    int mi = (int)m;
    return __fmul_rn(p, __int_as_float((mi + 127) << 23));
}

// ---- FROZEN: Eigen ptanh, fma-contracted, clamp 7.99881172180175781 ----
#define CLAMP_E 7.99881172180175781f
__device__ __forceinline__ float ptanh(float x) {
    float ax = fabsf(x);
    if (ax < 0.0004f) return x;
    float cx = fminf(fmaxf(x, -CLAMP_E), CLAMP_E);
    float x2 = __fmul_rn(cx, cx);
    float np = -2.76076847742355e-16f;
    np = fmaf(x2, np, 2.00018790482477e-13f);
    np = fmaf(x2, np, -8.60467152213735e-11f);
    np = fmaf(x2, np, 5.12229709037114e-08f);
    np = fmaf(x2, np, 1.48572235717979e-05f);
    np = fmaf(x2, np, 6.37261928875436e-04f);
    np = fmaf(x2, np, 4.89352455891786e-03f);
    np = __fmul_rn(cx, np);
    float dp = 1.19825839466702e-06f;
    dp = fmaf(x2, dp, 1.18534705686654e-04f);
    dp = fmaf(x2, dp, 2.26843463243900e-03f);
    dp = fmaf(x2, dp, 4.89352518554385e-03f);
    return __fdiv_rn(np, dp);
}

// ---- FROZEN: logistic = 1 / (1 + pexp(-x)) ----
__device__ __forceinline__ float plogistic(float v) {
    float e = pexp_fma(__fmul_rn(-1.0f, v));
    return __fdiv_rn(1.0f, __fadd_rn(1.0f, e));
}

// ============ probe: resolve mu/logvar layout from bias zero-pattern ============
__global__ void probe_kernel(const float* b0, const float* b1,
                             const float* b2, const float* b3,
                             const float* w0, const float* w1,
                             const float* w2, const float* w3) {
    if (threadIdx.x != 0 || blockIdx.x != 0) return;
    const float* bs[4] = {b0, b1, b2, b3};
    const float* wsrc[4] = {w0, w1, w2, w3};
    bool isMu[4];
    int nmu = 0;
    for (int i = 0; i < 4; i++) {
        bool z = true;
        for (int k = 0; k < 16; k++) z = z && (bs[i][k] == 0.0f);
        isMu[i] = z;
        if (z) nmu++;
    }
    int muSlot[2], lvSlot[2];
    if (nmu == 2) {
        int a = 0, c = 0;
        for (int i = 0; i < 4; i++) {
            if (isMu[i]) muSlot[a++] = i; else lvSlot[c++] = i;
        }
    } else {
        muSlot[0] = 0; lvSlot[0] = 1; muSlot[1] = 2; lvSlot[1] = 3;
    }
    g_pbmu0 = bs[muSlot[0]]; g_pbmu1 = bs[muSlot[1]];
    g_pblv0 = bs[lvSlot[0]]; g_pblv1 = bs[lvSlot[1]];
    g_pwmu0 = wsrc[muSlot[0]]; g_pwmu1 = wsrc[muSlot[1]];
    g_pwlv0 = wsrc[lvSlot[0]]; g_pwlv1 = wsrc[lvSlot[1]];
}

// ============ precompute: std = pexp(0.5*lv) ============
__global__ void pre_kernel(float* out) {
    const float* wlv0 = g_pwlv0;
    const float* wlv1 = g_pwlv1;
    const float* blv0 = g_pblv0;
    const float* blv1 = g_pblv1;
    int idx = blockIdx.x * blockDim.x + threadIdx.x;
    int stride = gridDim.x * blockDim.x;
    for (int i = idx; i < G4*Kd; i += stride) {
        g_std0[i] = pexp_fma(__fmul_rn(0.5f, wlv0[i]));
        g_std1[i] = pexp_fma(__fmul_rn(0.5f, wlv1[i]));
    }
    for (int i = idx; i < G4; i += stride) {
        g_bstd0[i] = pexp_fma(__fmul_rn(0.5f, blv0[i]));
        g_bstd1[i] = pexp_fma(__fmul_rn(0.5f, blv1[i]));
    }
    for (int i = idx; i < Bb*Hh; i += stride) { g_c0[i] = 0.f; g_c1[i] = 0.f; }
    if (idx == 0) out[KL_OFF] = 0.f;
}

// ============ KL reduction ============
__global__ void kl_kernel(float* out) {
    const float* wmu0 = g_pwmu0; const float* wlv0 = g_pwlv0;
    const float* wmu1 = g_pwmu1; const float* wlv1 = g_pwlv1;
    const float* bmu0 = g_pbmu0; const float* blv0 = g_pblv0;
    const float* bmu1 = g_pbmu1; const float* blv1 = g_pblv1;
    int idx = blockIdx.x * blockDim.x + threadIdx.x;
    int stride = gridDim.x * blockDim.x;
    float acc = 0.f;
    for (int i = idx; i < G4*Kd; i += stride) {
        float m = wmu0[i], v = wlv0[i]; acc += m*m + pexp_fma(v) - v;
        m = wmu1[i]; v = wlv1[i];       acc += m*m + pexp_fma(v) - v;
    }
    for (int i = idx; i < G4; i += stride) {
        float m = bmu0[i], v = blv0[i]; acc += m*m + pexp_fma(v) - v;
        m = bmu1[i]; v = blv1[i];       acc += m*m + pexp_fma(v) - v;
    }
    acc *= 0.5f;
    for (int o = 16; o; o >>= 1) acc += __shfl_down_sync(0xffffffffu, acc, o);
    __shared__ float sred[8];
    int lane = threadIdx.x & 31, w = threadIdx.x >> 5;
    if (lane == 0) sred[w] = acc;
    __syncthreads();
    if (w == 0) {
        acc = (lane < (int)(blockDim.x >> 5)) ? sred[lane] : 0.f;
        for (int o = 4; o; o >>= 1) acc += __shfl_down_sync(0xffffffffu, acc, o);
        if (lane == 0) atomicAdd(&out[KL_OFF], acc);
    }
}

// ============ tiled skewed step kernel — frozen arithmetic, optimized movement ============
// CTA tile: 32 batch x 16 hidden x 4 gates. 256 threads; thread owns 2b x 1j x 4g
// (8 fmaf chains). K=512 in 16 chunks of 32; double-buffered smem for both the
// activation tile (shared across j-threads -> 16x L1 traffic cut) and the sampled
// weight tile (eps-load latency hidden behind the FFMA block).
// Per-output arithmetic identical to R14: single sequential fmaf chain, k ascending.
__global__ void __launch_bounds__(256) step_kernel(
    int t,
    const float* __restrict__ x,
    const float* __restrict__ epsw0, const float* __restrict__ epsb0,
    const float* __restrict__ epsw1, const float* __restrict__ epsb1,
    float* __restrict__ out)
{
    const int layer = blockIdx.z;
    if (layer == 0 && t >= Lq) return;
    if (layer == 1 && t == 0) return;
    const int s = layer ? (t - 1) : t;

    const float* wmu  = layer ? g_pwmu1 : g_pwmu0;
    const float* bmu  = layer ? g_pbmu1 : g_pbmu0;
    const float* epsw = layer ? epsw1   : epsw0;
    const float* epsb = layer ? epsb1   : epsb0;
    const float* stdw = layer ? g_std1  : g_std0;
    const float* bstd = layer ? g_bstd1 : g_bstd0;
    float* cst = layer ? g_c1 : g_c0;

    const int m0 = blockIdx.x * 32;   // batch tile origin
    const int j0 = blockIdx.y * 16;   // hidden-col tile origin
    const int tid = threadIdx.x;

    __shared__ __align__(16) float As[2][32][34];      // [buf][k][m]
    __shared__ __align__(16) float Ws[2][4][32][17];   // [buf][gate][k][jj]

    float acc[4][2] = {};

    auto loadA = [&](int b, int k) -> float {
        if (layer == 0) {
            if (k < Iin) return x[((size_t)b*Lq + t)*Iin + k];
            return (t > 0) ? g_h0[(((size_t)(t-1)*Bb + b)*Hh) + (k - Iin)] : 0.f;
        } else {
            if (k < Hh) return g_h0[(((size_t)s*Bb + b)*Hh) + k];
            return (s > 0) ? out[(((size_t)b*Lq + (s-1))*Hh) + (k - Hh)] : 0.f;
        }
    };
    auto loadW = [&](int e, int kc) -> float {
        // e in [0,2048): col = e&31 (coalesced), jj = (e>>5)&15, g = e>>9
        int col = kc*32 + (e & 31);
        int jj  = (e >> 5) & 15;
        int g   = e >> 9;
        int row = g*Hh + j0 + jj;
        int wi  = row*Kd + col;
        size_t eo = ((size_t)s*G4 + row)*Kd + col;
        return fmaf(epsw[eo], stdw[wi], wmu[wi]);   // FROZEN sampling op
    };

    // prologue: stage chunk 0
    int buf = 0;
    #pragma unroll
    for (int i = 0; i < 4; i++) {
        int e = tid + i*256; int k = e & 31; int m = e >> 5;
        As[buf][k][m] = loadA(m0 + m, k);
    }
    #pragma unroll
    for (int i = 0; i < 8; i++) {
        int e = tid + i*256;
        Ws[buf][e >> 9][e & 31][(e >> 5) & 15] = loadW(e, 0);
    }
    __syncthreads();

    const int mi = tid & 15;
    const int jj = tid >> 4;

    for (int kc = 0; kc < 16; kc++) {
        float pa[4], pw[8];
        if (kc < 15) {
            #pragma unroll
            for (int i = 0; i < 4; i++) {
                int e = tid + i*256; int k = e & 31; int m = e >> 5;
                pa[i] = loadA(m0 + m, (kc+1)*32 + k);
            }
            #pragma unroll
            for (int i = 0; i < 8; i++) pw[i] = loadW(tid + i*256, kc+1);
        }
        #pragma unroll
        for (int k = 0; k < 32; k++) {
            float2 a = *(const float2*)&As[buf][k][mi*2];
            #pragma unroll
            for (int g = 0; g < 4; g++) {
                float bw = Ws[buf][g][k][jj];
                acc[g][0] = fmaf(a.x, bw, acc[g][0]);
                acc[g][1] = fmaf(a.y, bw, acc[g][1]);
            }
        }
        if (kc < 15) {
            int nb = buf ^ 1;
            #pragma unroll
            for (int i = 0; i < 4; i++) {
                int e = tid + i*256; As[nb][e & 31][e >> 5] = pa[i];
            }
            #pragma unroll
            for (int i = 0; i < 8; i++) {
                int e = tid + i*256;
                Ws[nb][e >> 9][e & 31][(e >> 5) & 15] = pw[i];
            }
            __syncthreads();
            buf = nb;
        }
    }

    // epilogue — FROZEN arithmetic (identical to R14)
    const int jcol = j0 + jj;
    float bb[4];
    #pragma unroll
    for (int g = 0; g < 4; g++) {
        int jg = g*Hh + jcol;
        bb[g] = fmaf(epsb[(size_t)s*G4 + jg], bstd[jg], bmu[jg]);
    }
    #pragma unroll
    for (int mm = 0; mm < 2; mm++) {
        int b = m0 + mi*2 + mm;
        float zi = __fadd_rn(acc[0][mm], bb[0]);
        float zf = __fadd_rn(acc[1][mm], bb[1]);
        float zg = __fadd_rn(acc[2][mm], bb[2]);
        float zo = __fadd_rn(acc[3][mm], bb[3]);
        float ig = plogistic(zi);
        float fg = plogistic(zf);
        float gg = ptanh(zg);
        float og = plogistic(zo);
        int ci = b*Hh + jcol;
        float cn = fmaf(fg, cst[ci], __fmul_rn(ig, gg));
        cst[ci] = cn;
        float h = __fmul_rn(og, ptanh(cn));
        if (layer == 0) g_h0[(((size_t)t*Bb + b)*Hh) + jcol] = h;
        else            out [(((size_t)b*Lq + s)*Hh) + jcol] = h;
    }
}

// ============ finalize ============
__global__ void final_kernel(float* out) {
    int idx = blockIdx.x * blockDim.x + threadIdx.x;
    if (idx < Bb*Hh) {
        int b = idx / Hh, j = idx % Hh;
        out[HF_OFF + idx]           = g_h0[((size_t)(Lq-1)*Bb)*Hh + idx];
        out[HF_OFF + Bb*Hh + idx]   = out[((size_t)b*Lq + (Lq-1))*Hh + j];
        out[CF_OFF + idx]           = g_c0[idx];
        out[CF_OFF + Bb*Hh + idx]   = g_c1[idx];
    }
}

// ============ launch ============
extern "C" void kernel_launch(void* const* d_in, const int* in_sizes, int n_in,
                              void* d_out, int out_size) {
    int xi = -1, wg[4], bg[4], ewg[2], ebg[2];
    int nw = 0, nb = 0, ne = 0, nber = 0;
    for (int i = 0; i < n_in; i++) {
        int sz = in_sizes[i];
        if (sz == Bb*Lq*Iin)            xi = i;
        else if (sz == G4*Kd)           { if (nw < 4)   wg[nw++]   = i; }
        else if (sz == G4)              { if (nb < 4)   bg[nb++]   = i; }
        else if (sz == Lq*G4*Kd)        { if (ne < 2)   ewg[ne++]  = i; }
        else if (sz == Lq*G4)           { if (nber < 2) ebg[nber++] = i; }
    }

    const float* x     = (const float*)d_in[xi];
    const float* epsw0 = (const float*)d_in[ewg[0]];
    const float* epsw1 = (const float*)d_in[ewg[1]];
    const float* epsb0 = (const float*)d_in[ebg[0]];
    const float* epsb1 = (const float*)d_in[ebg[1]];
    float* out = (float*)d_out;

    probe_kernel<<<1, 32>>>((const float*)d_in[bg[0]], (const float*)d_in[bg[1]],
                            (const float*)d_in[bg[2]], (const float*)d_in[bg[3]],
                            (const float*)d_in[wg[0]], (const float*)d_in[wg[1]],
                            (const float*)d_in[wg[2]], (const float*)d_in[wg[3]]);

    pre_kernel<<<512, 256>>>(out);
    kl_kernel<<<512, 256>>>(out);

    dim3 grid(4, 16, 2);   // 4 batch tiles x 16 hidden tiles x 2 layers (skewed)
    for (int t = 0; t <= Lq; t++) {
        step_kernel<<<grid, 256>>>(t, x, epsw0, epsb0, epsw1, epsb1, out);
    }
    final_kernel<<<128, 256>>>(out);
}

// round 16
// speedup vs baseline: 2.6505x; 2.6505x over previous
#include <cuda_runtime.h>
#include <cstdint>

#define Bb   128
#define Lq   128
#define Iin  256
#define Hh   256
#define G4   1024
#define Kd   512
#define NCTA 256

#define OUT_ELEMS (Bb*Lq*Hh)
#define HF_OFF (OUT_ELEMS)
#define CF_OFF (OUT_ELEMS + 2*Bb*Hh)
#define KL_OFF (OUT_ELEMS + 4*Bb*Hh)

// -------- scratch --------
__device__ float g_std0[G4*Kd];          // pexp(0.5*logvar)
__device__ float g_std1[G4*Kd];
__device__ float g_bstd0[G4], g_bstd1[G4];
__device__ float g_xT[(size_t)Lq*Iin*Bb];      // x transposed: [t][k][b]
__device__ float g_h0T[2*Hh*Bb];               // h0 parity buffers: [p][j][b]
__device__ float g_h1T[2*Hh*Bb];               // h1 parity buffers: [p][j][b]
__device__ unsigned g_bar_cnt;                 // grid barrier (self-resetting)
__device__ volatile unsigned g_bar_gen;

__device__ const float* g_pwmu0;
__device__ const float* g_pwlv0;
__device__ const float* g_pwmu1;
__device__ const float* g_pwlv1;
__device__ const float* g_pbmu0;
__device__ const float* g_pblv0;
__device__ const float* g_pbmu1;
__device__ const float* g_pblv1;

// ---- FROZEN: Cephes/XLA pexp, fma-contracted, clamp +-88.3762626647949 ----
__device__ __forceinline__ float pexp_fma(float x) {
    x = fminf(fmaxf(x, -88.3762626647949f), 88.3762626647949f);
    float m = floorf(fmaf(x, 1.44269504088896341f, 0.5f));
    float r = fmaf(m, -0.693359375f, x);
    r = fmaf(m, 2.12194440e-4f, r);
    float r2 = __fmul_rn(r, r);
    float p = 1.9875691500e-4f;
    p = fmaf(p, r, 1.3981999507e-3f);
    p = fmaf(p, r, 8.3334519073e-3f);
    p = fmaf(p, r, 4.1665795894e-2f);
    p = fmaf(p, r, 1.6666665459e-1f);
    p = fmaf(p, r, 5.0000001201e-1f);
    p = fmaf(p, r2, r);
    p = __fadd_rn(p, 1.0f);
    int mi = (int)m;
    return __fmul_rn(p, __int_as_float((mi + 127) << 23));
}

// ---- FROZEN: Eigen ptanh, fma-contracted, clamp 7.99881172180175781 ----
#define CLAMP_E 7.99881172180175781f
__device__ __forceinline__ float ptanh(float x) {
    float ax = fabsf(x);
    if (ax < 0.0004f) return x;
    float cx = fminf(fmaxf(x, -CLAMP_E), CLAMP_E);
    float x2 = __fmul_rn(cx, cx);
    float np = -2.76076847742355e-16f;
    np = fmaf(x2, np, 2.00018790482477e-13f);
    np = fmaf(x2, np, -8.60467152213735e-11f);
    np = fmaf(x2, np, 5.12229709037114e-08f);
    np = fmaf(x2, np, 1.48572235717979e-05f);
    np = fmaf(x2, np, 6.37261928875436e-04f);
    np = fmaf(x2, np, 4.89352455891786e-03f);
    np = __fmul_rn(cx, np);
    float dp = 1.19825839466702e-06f;
    dp = fmaf(x2, dp, 1.18534705686654e-04f);
    dp = fmaf(x2, dp, 2.26843463243900e-03f);
    dp = fmaf(x2, dp, 4.89352518554385e-03f);
    return __fdiv_rn(np, dp);
}

// ---- FROZEN: logistic = 1 / (1 + pexp(-x)) ----
__device__ __forceinline__ float plogistic(float v) {
    float e = pexp_fma(__fmul_rn(-1.0f, v));
    return __fdiv_rn(1.0f, __fadd_rn(1.0f, e));
}

// ============ probe: resolve mu/logvar layout from bias zero-pattern ============
__global__ void probe_kernel(const float* b0, const float* b1,
                             const float* b2, const float* b3,
                             const float* w0, const float* w1,
                             const float* w2, const float* w3) {
    if (threadIdx.x != 0 || blockIdx.x != 0) return;
    const float* bs[4] = {b0, b1, b2, b3};
    const float* wsrc[4] = {w0, w1, w2, w3};
    bool isMu[4];
    int nmu = 0;
    for (int i = 0; i < 4; i++) {
        bool z = true;
        for (int k = 0; k < 16; k++) z = z && (bs[i][k] == 0.0f);
        isMu[i] = z;
        if (z) nmu++;
    }
    int muSlot[2], lvSlot[2];
    if (nmu == 2) {
        int a = 0, c = 0;
        for (int i = 0; i < 4; i++) {
            if (isMu[i]) muSlot[a++] = i; else lvSlot[c++] = i;
        }
    } else {
        muSlot[0] = 0; lvSlot[0] = 1; muSlot[1] = 2; lvSlot[1] = 3;
    }
    g_pbmu0 = bs[muSlot[0]]; g_pbmu1 = bs[muSlot[1]];
    g_pblv0 = bs[lvSlot[0]]; g_pblv1 = bs[lvSlot[1]];
    g_pwmu0 = wsrc[muSlot[0]]; g_pwmu1 = wsrc[muSlot[1]];
    g_pwlv0 = wsrc[lvSlot[0]]; g_pwlv1 = wsrc[lvSlot[1]];
}

// ============ precompute: std = pexp(0.5*lv) ============
__global__ void pre_kernel(float* out) {
    const float* wlv0 = g_pwlv0;
    const float* wlv1 = g_pwlv1;
    const float* blv0 = g_pblv0;
    const float* blv1 = g_pblv1;
    int idx = blockIdx.x * blockDim.x + threadIdx.x;
    int stride = gridDim.x * blockDim.x;
    for (int i = idx; i < G4*Kd; i += stride) {
        g_std0[i] = pexp_fma(__fmul_rn(0.5f, wlv0[i]));
        g_std1[i] = pexp_fma(__fmul_rn(0.5f, wlv1[i]));
    }
    for (int i = idx; i < G4; i += stride) {
        g_bstd0[i] = pexp_fma(__fmul_rn(0.5f, blv0[i]));
        g_bstd1[i] = pexp_fma(__fmul_rn(0.5f, blv1[i]));
    }
    if (idx == 0) out[KL_OFF] = 0.f;
}

// ============ transpose x: [b][t][k] -> [t][k][b] ============
__global__ void transpose_x(const float* __restrict__ x) {
    int idx = blockIdx.x * blockDim.x + threadIdx.x;
    int stride = gridDim.x * blockDim.x;
    for (int i = idx; i < Lq*Iin*Bb; i += stride) {
        int k = i & 255;           // lane varies k -> coalesced reads
        int b = (i >> 8) & 127;
        int t = i >> 15;
        g_xT[((size_t)t*Iin + k)*Bb + b] = x[((size_t)b*Lq + t)*Iin + k];
    }
}

// ============ KL reduction ============
__global__ void kl_kernel(float* out) {
    const float* wmu0 = g_pwmu0; const float* wlv0 = g_pwlv0;
    const float* wmu1 = g_pwmu1; const float* wlv1 = g_pwlv1;
    const float* bmu0 = g_pbmu0; const float* blv0 = g_pblv0;
    const float* bmu1 = g_pbmu1; const float* blv1 = g_pblv1;
    int idx = blockIdx.x * blockDim.x + threadIdx.x;
    int stride = gridDim.x * blockDim.x;
    float acc = 0.f;
    for (int i = idx; i < G4*Kd; i += stride) {
        float m = wmu0[i], v = wlv0[i]; acc += m*m + pexp_fma(v) - v;
        m = wmu1[i]; v = wlv1[i];       acc += m*m + pexp_fma(v) - v;
    }
    for (int i = idx; i < G4; i += stride) {
        float m = bmu0[i], v = blv0[i]; acc += m*m + pexp_fma(v) - v;
        m = bmu1[i]; v = blv1[i];       acc += m*m + pexp_fma(v) - v;
    }
    acc *= 0.5f;
    for (int o = 16; o; o >>= 1) acc += __shfl_down_sync(0xffffffffu, acc, o);
    __shared__ float sred[8];
    int lane = threadIdx.x & 31, w = threadIdx.x >> 5;
    if (lane == 0) sred[w] = acc;
    __syncthreads();
    if (w == 0) {
        acc = (lane < (int)(blockDim.x >> 5)) ? sred[lane] : 0.f;
        for (int o = 4; o; o >>= 1) acc += __shfl_down_sync(0xffffffffu, acc, o);
        if (lane == 0) atomicAdd(&out[KL_OFF], acc);
    }
}

// ---- software grid barrier (all NCTA CTAs resident by construction) ----
__device__ __forceinline__ void grid_barrier() {
    __syncthreads();
    if (threadIdx.x == 0) {
        unsigned g = g_bar_gen;               // read BEFORE arriving
        __threadfence();                      // publish this CTA's writes
        if (atomicAdd(&g_bar_cnt, 1u) == NCTA - 1u) {
            g_bar_cnt = 0u;
            __threadfence();
            g_bar_gen = g + 1u;
        } else {
            while (g_bar_gen == g) { __nanosleep(100); }
        }
        __threadfence();                      // gpu-scope: invalidates L1 (CCTL.IVALL)
    }
    __syncthreads();
}

// ============ persistent step kernel — frozen arithmetic, fused time loop ============
// 256 CTAs x 256 threads. CTA = (layer, 2 hidden cols). Thread = (b, j), owns the 4
// gate chains + c-state in registers for all 128 steps. Weights sampled cooperatively
// into double-buffered smem; activations read coalesced from transposed state buffers.
// Per-output arithmetic identical to R14 (sequential fmaf chain, k ascending 0..511).
__global__ void __launch_bounds__(256, 2) step_persist(
    const float* __restrict__ epsw0, const float* __restrict__ epsb0,
    const float* __restrict__ epsw1, const float* __restrict__ epsb1,
    float* __restrict__ out)
{
    const int bid   = blockIdx.x;
    const int layer = bid & 1;
    const int j0    = (bid >> 1) * 2;
    const int tid   = threadIdx.x;
    const int b     = tid & 127;
    const int jj    = tid >> 7;           // 0..1
    const int j     = j0 + jj;

    const float* wmu  = layer ? g_pwmu1 : g_pwmu0;
    const float* bmu  = layer ? g_pbmu1 : g_pbmu0;
    const float* epsw = layer ? epsw1   : epsw0;
    const float* epsb = layer ? epsb1   : epsb0;
    const float* stdw = layer ? g_std1  : g_std0;
    const float* bstd = layer ? g_bstd1 : g_bstd0;

    // weight-sampling assignment: thread samples rows (g=i, own jj) at col = b
    int wrow[4];
    #pragma unroll
    for (int i = 0; i < 4; i++) wrow[i] = i*Hh + j;

    __shared__ __align__(16) float Ws[2][128][12];   // [buf][k][jj*4+g] (pad 12)

    float c_reg = 0.f;
    float h_last = 0.f;

    for (int tt = 0; tt <= Lq; tt++) {
        const bool active = layer ? (tt >= 1) : (tt < Lq);
        const int s = layer ? (tt - 1) : tt;

        if (active) {
            // ---- prologue: sample chunk 0 into buffer 0 ----
            #pragma unroll
            for (int i = 0; i < 4; i++) {
                int col = b;                       // chunk 0
                int wi = wrow[i]*Kd + col;
                size_t eo = ((size_t)s*G4 + wrow[i])*Kd + col;
                Ws[0][b][jj*4 + i] = fmaf(epsw[eo], stdw[wi], wmu[wi]);
            }
            __syncthreads();

            float a0 = 0.f, a1 = 0.f, a2 = 0.f, a3 = 0.f;
            int buf = 0;

            #pragma unroll
            for (int ck = 0; ck < 4; ck++) {
                // prefetch next chunk's samples into registers (hides eps DRAM latency)
                float sv0, sv1, sv2, sv3;
                if (ck < 3) {
                    int col = (ck + 1)*128 + b;
                    int wi0 = wrow[0]*Kd + col;
                    int wi1 = wrow[1]*Kd + col;
                    int wi2 = wrow[2]*Kd + col;
                    int wi3 = wrow[3]*Kd + col;
                    size_t e0 = ((size_t)s*G4 + wrow[0])*Kd + col;
                    size_t e1 = ((size_t)s*G4 + wrow[1])*Kd + col;
                    size_t e2 = ((size_t)s*G4 + wrow[2])*Kd + col;
                    size_t e3 = ((size_t)s*G4 + wrow[3])*Kd + col;
                    sv0 = fmaf(epsw[e0], stdw[wi0], wmu[wi0]);
                    sv1 = fmaf(epsw[e1], stdw[wi1], wmu[wi1]);
                    sv2 = fmaf(epsw[e2], stdw[wi2], wmu[wi2]);
                    sv3 = fmaf(epsw[e3], stdw[wi3], wmu[wi3]);
                }

                // activation source for this chunk (coalesced: lane = b)
                const float* ab = nullptr;
                if (layer == 0) {
                    if (ck < 2) ab = g_xT + ((size_t)tt*Iin + ck*128)*Bb + b;
                    else if (tt > 0) ab = g_h0T + (size_t)((tt-1) & 1)*Hh*Bb + (ck-2)*128*Bb + b;
                } else {
                    if (ck < 2) ab = g_h0T + (size_t)(s & 1)*Hh*Bb + ck*128*Bb + b;
                    else if (s > 0) ab = g_h1T + (size_t)((s-1) & 1)*Hh*Bb + (ck-2)*128*Bb + b;
                }

                if (ab != nullptr) {
                    #pragma unroll 16
                    for (int kk = 0; kk < 128; kk++) {
                        float av = ab[(size_t)kk*Bb];
                        float4 w4 = *reinterpret_cast<const float4*>(&Ws[buf][kk][jj*4]);
                        a0 = fmaf(av, w4.x, a0);
                        a1 = fmaf(av, w4.y, a1);
                        a2 = fmaf(av, w4.z, a2);
                        a3 = fmaf(av, w4.w, a3);
                    }
                }

                if (ck < 3) {
                    int nb = buf ^ 1;
                    Ws[nb][b][jj*4 + 0] = sv0;
                    Ws[nb][b][jj*4 + 1] = sv1;
                    Ws[nb][b][jj*4 + 2] = sv2;
                    Ws[nb][b][jj*4 + 3] = sv3;
                    __syncthreads();
                    buf = nb;
                }
            }

            // ---- epilogue: FROZEN gate/cell arithmetic ----
            float bb0 = fmaf(epsb[(size_t)s*G4 + 0*Hh + j], bstd[0*Hh + j], bmu[0*Hh + j]);
            float bb1 = fmaf(epsb[(size_t)s*G4 + 1*Hh + j], bstd[1*Hh + j], bmu[1*Hh + j]);
            float bb2 = fmaf(epsb[(size_t)s*G4 + 2*Hh + j], bstd[2*Hh + j], bmu[2*Hh + j]);
            float bb3 = fmaf(epsb[(size_t)s*G4 + 3*Hh + j], bstd[3*Hh + j], bmu[3*Hh + j]);

            float zi = __fadd_rn(a0, bb0);
            float zf = __fadd_rn(a1, bb1);
            float zg = __fadd_rn(a2, bb2);
            float zo = __fadd_rn(a3, bb3);

            float ig = plogistic(zi);
            float fg = plogistic(zf);
            float gg = ptanh(zg);
            float og = plogistic(zo);

            c_reg = fmaf(fg, c_reg, __fmul_rn(ig, gg));
            float h = __fmul_rn(og, ptanh(c_reg));
            h_last = h;

            if (layer == 0) {
                g_h0T[(size_t)(tt & 1)*Hh*Bb + (size_t)j*Bb + b] = h;
            } else {
                g_h1T[(size_t)(s & 1)*Hh*Bb + (size_t)j*Bb + b] = h;
                out[((size_t)b*Lq + s)*Hh + j] = h;
            }
        }

        grid_barrier();
    }

    // finals from registers
    out[HF_OFF + (size_t)layer*Bb*Hh + (size_t)b*Hh + j] = h_last;
    out[CF_OFF + (size_t)layer*Bb*Hh + (size_t)b*Hh + j] = c_reg;
}

// ============ launch ============
extern "C" void kernel_launch(void* const* d_in, const int* in_sizes, int n_in,
                              void* d_out, int out_size) {
    int xi = -1, wg[4], bg[4], ewg[2], ebg[2];
    int nw = 0, nb = 0, ne = 0, nber = 0;
    for (int i = 0; i < n_in; i++) {
        int sz = in_sizes[i];
        if (sz == Bb*Lq*Iin)            xi = i;
        else if (sz == G4*Kd)           { if (nw < 4)   wg[nw++]   = i; }
        else if (sz == G4)              { if (nb < 4)   bg[nb++]   = i; }
        else if (sz == Lq*G4*Kd)        { if (ne < 2)   ewg[ne++]  = i; }
        else if (sz == Lq*G4)           { if (nber < 2) ebg[nber++] = i; }
    }

    const float* x     = (const float*)d_in[xi];
    const float* epsw0 = (const float*)d_in[ewg[0]];
    const float* epsw1 = (const float*)d_in[ewg[1]];
    const float* epsb0 = (const float*)d_in[ebg[0]];
    const float* epsb1 = (const float*)d_in[ebg[1]];
    float* out = (float*)d_out;

    probe_kernel<<<1, 32>>>((const float*)d_in[bg[0]], (const float*)d_in[bg[1]],
                            (const float*)d_in[bg[2]], (const float*)d_in[bg[3]],
                            (const float*)d_in[wg[0]], (const float*)d_in[wg[1]],
                            (const float*)d_in[wg[2]], (const float*)d_in[wg[3]]);

    pre_kernel<<<512, 256>>>(out);
    transpose_x<<<512, 256>>>(x);
    kl_kernel<<<512, 256>>>(out);

    step_persist<<<NCTA, 256>>>(epsw0, epsb0, epsw1, epsb1, out);
}

// round 17
// speedup vs baseline: 3.2295x; 1.2184x over previous
#include <cuda_runtime.h>
#include <cstdint>

#define Bb   128
#define Lq   128
#define Iin  256
#define Hh   256
#define G4   1024
#define Kd   512
#define NCTA 256

#define OUT_ELEMS (Bb*Lq*Hh)
#define HF_OFF (OUT_ELEMS)
#define CF_OFF (OUT_ELEMS + 2*Bb*Hh)
#define KL_OFF (OUT_ELEMS + 4*Bb*Hh)

// -------- scratch --------
__device__ float g_std0[G4*Kd];          // pexp(0.5*logvar)
__device__ float g_std1[G4*Kd];
__device__ float g_bstd0[G4], g_bstd1[G4];
__device__ float g_xT[(size_t)Lq*Iin*Bb];      // x transposed: [t][k][b]
__device__ float g_h0T[2*Hh*Bb];               // h0 parity buffers: [p][j][b]
__device__ float g_h1T[2*Hh*Bb];               // h1 parity buffers: [p][j][b]
__device__ unsigned g_bar_cnt;
__device__ volatile unsigned g_bar_gen;

__device__ const float* g_pwmu0;
__device__ const float* g_pwlv0;
__device__ const float* g_pwmu1;
__device__ const float* g_pwlv1;
__device__ const float* g_pbmu0;
__device__ const float* g_pblv0;
__device__ const float* g_pbmu1;
__device__ const float* g_pblv1;

// ---- FROZEN: Cephes/XLA pexp, fma-contracted, clamp +-88.3762626647949 ----
__device__ __forceinline__ float pexp_fma(float x) {
    x = fminf(fmaxf(x, -88.3762626647949f), 88.3762626647949f);
    float m = floorf(fmaf(x, 1.44269504088896341f, 0.5f));
    float r = fmaf(m, -0.693359375f, x);
    r = fmaf(m, 2.12194440e-4f, r);
    float r2 = __fmul_rn(r, r);
    float p = 1.9875691500e-4f;
    p = fmaf(p, r, 1.3981999507e-3f);
    p = fmaf(p, r, 8.3334519073e-3f);
    p = fmaf(p, r, 4.1665795894e-2f);
    p = fmaf(p, r, 1.6666665459e-1f);
    p = fmaf(p, r, 5.0000001201e-1f);
    p = fmaf(p, r2, r);
    p = __fadd_rn(p, 1.0f);
    int mi = (int)m;
    return __fmul_rn(p, __int_as_float((mi + 127) << 23));
}

// ---- FROZEN: Eigen ptanh, fma-contracted, clamp 7.99881172180175781 ----
#define CLAMP_E 7.99881172180175781f
__device__ __forceinline__ float ptanh(float x) {
    float ax = fabsf(x);
    if (ax < 0.0004f) return x;
    float cx = fminf(fmaxf(x, -CLAMP_E), CLAMP_E);
    float x2 = __fmul_rn(cx, cx);
    float np = -2.76076847742355e-16f;
    np = fmaf(x2, np, 2.00018790482477e-13f);
    np = fmaf(x2, np, -8.60467152213735e-11f);
    np = fmaf(x2, np, 5.12229709037114e-08f);
    np = fmaf(x2, np, 1.48572235717979e-05f);
    np = fmaf(x2, np, 6.37261928875436e-04f);
    np = fmaf(x2, np, 4.89352455891786e-03f);
    np = __fmul_rn(cx, np);
    float dp = 1.19825839466702e-06f;
    dp = fmaf(x2, dp, 1.18534705686654e-04f);
    dp = fmaf(x2, dp, 2.26843463243900e-03f);
    dp = fmaf(x2, dp, 4.89352518554385e-03f);
    return __fdiv_rn(np, dp);
}

// ---- FROZEN: logistic = 1 / (1 + pexp(-x)) ----
__device__ __forceinline__ float plogistic(float v) {
    float e = pexp_fma(__fmul_rn(-1.0f, v));
    return __fdiv_rn(1.0f, __fadd_rn(1.0f, e));
}

// ============ probe: resolve mu/logvar layout from bias zero-pattern ============
__global__ void probe_kernel(const float* b0, const float* b1,
                             const float* b2, const float* b3,
                             const float* w0, const float* w1,
                             const float* w2, const float* w3) {
    if (threadIdx.x != 0 || blockIdx.x != 0) return;
    const float* bs[4] = {b0, b1, b2, b3};
    const float* wsrc[4] = {w0, w1, w2, w3};
    bool isMu[4];
    int nmu = 0;
    for (int i = 0; i < 4; i++) {
        bool z = true;
        for (int k = 0; k < 16; k++) z = z && (bs[i][k] == 0.0f);
        isMu[i] = z;
        if (z) nmu++;
    }
    int muSlot[2], lvSlot[2];
    if (nmu == 2) {
        int a = 0, c = 0;
        for (int i = 0; i < 4; i++) {
            if (isMu[i]) muSlot[a++] = i; else lvSlot[c++] = i;
        }
    } else {
        muSlot[0] = 0; lvSlot[0] = 1; muSlot[1] = 2; lvSlot[1] = 3;
    }
    g_pbmu0 = bs[muSlot[0]]; g_pbmu1 = bs[muSlot[1]];
    g_pblv0 = bs[lvSlot[0]]; g_pblv1 = bs[lvSlot[1]];
    g_pwmu0 = wsrc[muSlot[0]]; g_pwmu1 = wsrc[muSlot[1]];
    g_pwlv0 = wsrc[lvSlot[0]]; g_pwlv1 = wsrc[lvSlot[1]];
}

// ============ precompute: std = pexp(0.5*lv) ============
__global__ void pre_kernel(float* out) {
    const float* wlv0 = g_pwlv0;
    const float* wlv1 = g_pwlv1;
    const float* blv0 = g_pblv0;
    const float* blv1 = g_pblv1;
    int idx = blockIdx.x * blockDim.x + threadIdx.x;
    int stride = gridDim.x * blockDim.x;
    for (int i = idx; i < G4*Kd; i += stride) {
        g_std0[i] = pexp_fma(__fmul_rn(0.5f, wlv0[i]));
        g_std1[i] = pexp_fma(__fmul_rn(0.5f, wlv1[i]));
    }
    for (int i = idx; i < G4; i += stride) {
        g_bstd0[i] = pexp_fma(__fmul_rn(0.5f, blv0[i]));
        g_bstd1[i] = pexp_fma(__fmul_rn(0.5f, blv1[i]));
    }
    if (idx == 0) out[KL_OFF] = 0.f;
}

// ============ transpose x: [b][t][k] -> [t][k][b] ============
__global__ void transpose_x(const float* __restrict__ x) {
    int idx = blockIdx.x * blockDim.x + threadIdx.x;
    int stride = gridDim.x * blockDim.x;
    for (int i = idx; i < Lq*Iin*Bb; i += stride) {
        int k = i & 255;
        int b = (i >> 8) & 127;
        int t = i >> 15;
        g_xT[((size_t)t*Iin + k)*Bb + b] = x[((size_t)b*Lq + t)*Iin + k];
    }
}

// ============ KL reduction ============
__global__ void kl_kernel(float* out) {
    const float* wmu0 = g_pwmu0; const float* wlv0 = g_pwlv0;
    const float* wmu1 = g_pwmu1; const float* wlv1 = g_pwlv1;
    const float* bmu0 = g_pbmu0; const float* blv0 = g_pblv0;
    const float* bmu1 = g_pbmu1; const float* blv1 = g_pblv1;
    int idx = blockIdx.x * blockDim.x + threadIdx.x;
    int stride = gridDim.x * blockDim.x;
    float acc = 0.f;
    for (int i = idx; i < G4*Kd; i += stride) {
        float m = wmu0[i], v = wlv0[i]; acc += m*m + pexp_fma(v) - v;
        m = wmu1[i]; v = wlv1[i];       acc += m*m + pexp_fma(v) - v;
    }
    for (int i = idx; i < G4; i += stride) {
        float m = bmu0[i], v = blv0[i]; acc += m*m + pexp_fma(v) - v;
        m = bmu1[i]; v = blv1[i];       acc += m*m + pexp_fma(v) - v;
    }
    acc *= 0.5f;
    for (int o = 16; o; o >>= 1) acc += __shfl_down_sync(0xffffffffu, acc, o);
    __shared__ float sred[8];
    int lane = threadIdx.x & 31, w = threadIdx.x >> 5;
    if (lane == 0) sred[w] = acc;
    __syncthreads();
    if (w == 0) {
        acc = (lane < (int)(blockDim.x >> 5)) ? sred[lane] : 0.f;
        for (int o = 4; o; o >>= 1) acc += __shfl_down_sync(0xffffffffu, acc, o);
        if (lane == 0) atomicAdd(&out[KL_OFF], acc);
    }
}

// ---- software grid barrier ----
__device__ __forceinline__ void grid_barrier() {
    __syncthreads();
    if (threadIdx.x == 0) {
        unsigned g = g_bar_gen;
        __threadfence();
        if (atomicAdd(&g_bar_cnt, 1u) == NCTA - 1u) {
            g_bar_cnt = 0u;
            __threadfence();
            g_bar_gen = g + 1u;
        } else {
            while (g_bar_gen == g) { __nanosleep(100); }
        }
        __threadfence();
    }
    __syncthreads();
}

// ============ persistent step kernel — frozen arithmetic, f32x2 packed FMA ============
// Per-gate chains are packed pairwise into fma.rn.f32x2: acc_if = (acc_i, acc_f),
// acc_go = (acc_g, acc_o). Each half is an independent IEEE fma.rn chain with the
// exact same k-ascending order as R16 -> bit-identical results at half the FMA
// instruction count (SASS FFMA2).
__global__ void __launch_bounds__(256, 2) step_persist(
    const float* __restrict__ epsw0, const float* __restrict__ epsb0,
    const float* __restrict__ epsw1, const float* __restrict__ epsb1,
    float* __restrict__ out)
{
    const int bid   = blockIdx.x;
    const int layer = bid & 1;
    const int j0    = (bid >> 1) * 2;
    const int tid   = threadIdx.x;
    const int b     = tid & 127;
    const int jj    = tid >> 7;           // 0..1
    const int j     = j0 + jj;

    const float* wmu  = layer ? g_pwmu1 : g_pwmu0;
    const float* bmu  = layer ? g_pbmu1 : g_pbmu0;
    const float* epsw = layer ? epsw1   : epsw0;
    const float* epsb = layer ? epsb1   : epsb0;
    const float* stdw = layer ? g_std1  : g_std0;
    const float* bstd = layer ? g_bstd1 : g_bstd0;

    int wrow[4];
    #pragma unroll
    for (int i = 0; i < 4; i++) wrow[i] = i*Hh + j;

    __shared__ __align__(16) float Ws[2][128][12];   // [buf][k][jj*4+g]

    float c_reg = 0.f;
    float h_last = 0.f;

    for (int tt = 0; tt <= Lq; tt++) {
        const bool active = layer ? (tt >= 1) : (tt < Lq);
        const int s = layer ? (tt - 1) : tt;

        if (active) {
            // ---- prologue: sample chunk 0 ----
            #pragma unroll
            for (int i = 0; i < 4; i++) {
                int col = b;
                int wi = wrow[i]*Kd + col;
                size_t eo = ((size_t)s*G4 + wrow[i])*Kd + col;
                Ws[0][b][jj*4 + i] = fmaf(epsw[eo], stdw[wi], wmu[wi]);
            }
            __syncthreads();

            unsigned long long acc_if = 0ull;   // (i, f) packed fp32x2
            unsigned long long acc_go = 0ull;   // (g, o) packed fp32x2
            int buf = 0;

            #pragma unroll
            for (int ck = 0; ck < 4; ck++) {
                // prefetch next chunk's samples (hides eps DRAM latency)
                float sv0, sv1, sv2, sv3;
                if (ck < 3) {
                    int col = (ck + 1)*128 + b;
                    int wi0 = wrow[0]*Kd + col;
                    int wi1 = wrow[1]*Kd + col;
                    int wi2 = wrow[2]*Kd + col;
                    int wi3 = wrow[3]*Kd + col;
                    size_t e0 = ((size_t)s*G4 + wrow[0])*Kd + col;
                    size_t e1 = ((size_t)s*G4 + wrow[1])*Kd + col;
                    size_t e2 = ((size_t)s*G4 + wrow[2])*Kd + col;
                    size_t e3 = ((size_t)s*G4 + wrow[3])*Kd + col;
                    sv0 = fmaf(epsw[e0], stdw[wi0], wmu[wi0]);
                    sv1 = fmaf(epsw[e1], stdw[wi1], wmu[wi1]);
                    sv2 = fmaf(epsw[e2], stdw[wi2], wmu[wi2]);
                    sv3 = fmaf(epsw[e3], stdw[wi3], wmu[wi3]);
                }

                const float* ab = nullptr;
                if (layer == 0) {
                    if (ck < 2) ab = g_xT + ((size_t)tt*Iin + ck*128)*Bb + b;
                    else if (tt > 0) ab = g_h0T + (size_t)((tt-1) & 1)*Hh*Bb + (ck-2)*128*Bb + b;
                } else {
                    if (ck < 2) ab = g_h0T + (size_t)(s & 1)*Hh*Bb + ck*128*Bb + b;
                    else if (s > 0) ab = g_h1T + (size_t)((s-1) & 1)*Hh*Bb + (ck-2)*128*Bb + b;
                }

                if (ab != nullptr) {
                    #pragma unroll
                    for (int kk = 0; kk < 128; kk += 8) {
                        float av[8];
                        #pragma unroll
                        for (int u = 0; u < 8; u++) av[u] = ab[(size_t)(kk+u)*Bb];
                        #pragma unroll
                        for (int u = 0; u < 8; u++) {
                            unsigned avu = __float_as_uint(av[u]);
                            unsigned long long av2;
                            asm("mov.b64 %0, {%1, %1};" : "=l"(av2) : "r"(avu));
                            const ulonglong2 w2 =
                                *reinterpret_cast<const ulonglong2*>(&Ws[buf][kk+u][jj*4]);
                            asm("fma.rn.f32x2 %0, %1, %2, %0;"
                                : "+l"(acc_if) : "l"(av2), "l"(w2.x));
                            asm("fma.rn.f32x2 %0, %1, %2, %0;"
                                : "+l"(acc_go) : "l"(av2), "l"(w2.y));
                        }
                    }
                }

                if (ck < 3) {
                    int nb = buf ^ 1;
                    Ws[nb][b][jj*4 + 0] = sv0;
                    Ws[nb][b][jj*4 + 1] = sv1;
                    Ws[nb][b][jj*4 + 2] = sv2;
                    Ws[nb][b][jj*4 + 3] = sv3;
                    __syncthreads();
                    buf = nb;
                }
            }

            // unpack accumulators
            unsigned u0, u1, u2, u3;
            asm("mov.b64 {%0, %1}, %2;" : "=r"(u0), "=r"(u1) : "l"(acc_if));
            asm("mov.b64 {%0, %1}, %2;" : "=r"(u2), "=r"(u3) : "l"(acc_go));
            float a0 = __uint_as_float(u0);
            float a1 = __uint_as_float(u1);
            float a2 = __uint_as_float(u2);
            float a3 = __uint_as_float(u3);

            // ---- epilogue: FROZEN gate/cell arithmetic ----
            float bb0 = fmaf(epsb[(size_t)s*G4 + 0*Hh + j], bstd[0*Hh + j], bmu[0*Hh + j]);
            float bb1 = fmaf(epsb[(size_t)s*G4 + 1*Hh + j], bstd[1*Hh + j], bmu[1*Hh + j]);
            float bb2 = fmaf(epsb[(size_t)s*G4 + 2*Hh + j], bstd[2*Hh + j], bmu[2*Hh + j]);
            float bb3 = fmaf(epsb[(size_t)s*G4 + 3*Hh + j], bstd[3*Hh + j], bmu[3*Hh + j]);

            float zi = __fadd_rn(a0, bb0);
            float zf = __fadd_rn(a1, bb1);
            float zg = __fadd_rn(a2, bb2);
            float zo = __fadd_rn(a3, bb3);

            float ig = plogistic(zi);
            float fg = plogistic(zf);
            float gg = ptanh(zg);
            float og = plogistic(zo);

            c_reg = fmaf(fg, c_reg, __fmul_rn(ig, gg));
            float h = __fmul_rn(og, ptanh(c_reg));
            h_last = h;

            if (layer == 0) {
                g_h0T[(size_t)(tt & 1)*Hh*Bb + (size_t)j*Bb + b] = h;
            } else {
                g_h1T[(size_t)(s & 1)*Hh*Bb + (size_t)j*Bb + b] = h;
                out[((size_t)b*Lq + s)*Hh + j] = h;
            }
        }

        grid_barrier();
    }

    out[HF_OFF + (size_t)layer*Bb*Hh + (size_t)b*Hh + j] = h_last;
    out[CF_OFF + (size_t)layer*Bb*Hh + (size_t)b*Hh + j] = c_reg;
}

// ============ launch ============
extern "C" void kernel_launch(void* const* d_in, const int* in_sizes, int n_in,
                              void* d_out, int out_size) {
    int xi = -1, wg[4], bg[4], ewg[2], ebg[2];
    int nw = 0, nb = 0, ne = 0, nber = 0;
    for (int i = 0; i < n_in; i++) {
        int sz = in_sizes[i];
        if (sz == Bb*Lq*Iin)            xi = i;
        else if (sz == G4*Kd)           { if (nw < 4)   wg[nw++]   = i; }
        else if (sz == G4)              { if (nb < 4)   bg[nb++]   = i; }
        else if (sz == Lq*G4*Kd)        { if (ne < 2)   ewg[ne++]  = i; }
        else if (sz == Lq*G4)           { if (nber < 2) ebg[nber++] = i; }
    }

    const float* x     = (const float*)d_in[xi];
    const float* epsw0 = (const float*)d_in[ewg[0]];
    const float* epsw1 = (const float*)d_in[ewg[1]];
    const float* epsb0 = (const float*)d_in[ebg[0]];
    const float* epsb1 = (const float*)d_in[ebg[1]];
    float* out = (float*)d_out;

    probe_kernel<<<1, 32>>>((const float*)d_in[bg[0]], (const float*)d_in[bg[1]],
                            (const float*)d_in[bg[2]], (const float*)d_in[bg[3]],
                            (const float*)d_in[wg[0]], (const float*)d_in[wg[1]],
                            (const float*)d_in[wg[2]], (const float*)d_in[wg[3]]);

    pre_kernel<<<512, 256>>>(out);
    transpose_x<<<512, 256>>>(x);
    kl_kernel<<<512, 256>>>(out);

    step_persist<<<NCTA, 256>>>(epsw0, epsb0, epsw1, epsb1, out);
}